// round 3
// baseline (speedup 1.0000x reference)
#include <cuda_runtime.h>
#include <math.h>

// Problem constants
#define VN   10000
#define VOUT 10001
#define EE   256
#define HH   512
#define G3   1536
#define BB   64
#define TT   128
#define NR   8192            // BB*TT
#define K_LOC_ELEMS ((size_t)NR * VN)   // 81,920,000 floats of location logits

// Scratch (device globals; no allocations allowed)
__device__ float g_xp[(size_t)NR * G3];     // input-gate projections for current layer
__device__ float g_h [(size_t)NR * HH];     // layer output sequence (h1, then h2)
__device__ float g_state[BB * HH];          // recurrent state h_{t-1}
__device__ float g_ghp[4][BB * G3];         // split-K partials of h @ W_hh^T

// ---------------------------------------------------------------------------
// Zero the recurrent state
// ---------------------------------------------------------------------------
__global__ void k_zero_state() {
    int i = blockIdx.x * blockDim.x + threadIdx.x;
    if (i < BB * HH) g_state[i] = 0.0f;
}

// ---------------------------------------------------------------------------
// proj0: g_xp[n,g] = sum_e emb[loc[n],e]*w0[g,e] + times[n]*w0[g,256] + b0[g]
// Tiles: BM=64, BN=64, BK=16, 256 threads, 4x4 per thread.
// ---------------------------------------------------------------------------
__global__ void __launch_bounds__(256)
k_proj0(const int* __restrict__ loc, const float* __restrict__ times,
        const float* __restrict__ emb, const float* __restrict__ w0,
        const float* __restrict__ b0)
{
    __shared__ float As[16][64];
    __shared__ float Ws[16][64];
    __shared__ int   locs[64];
    __shared__ float ts[64];

    const int tid   = threadIdx.x;
    const int mtile = blockIdx.y * 64;
    const int ntile = blockIdx.x * 64;
    if (tid < 64) { locs[tid] = loc[mtile + tid]; ts[tid] = times[mtile + tid]; }
    __syncthreads();

    const int tx = tid & 15, ty = tid >> 4;
    const int lm = tid >> 2;             // 0..63
    const int lk = (tid & 3) << 2;       // 0,4,8,12
    const int arow = locs[lm];
    const float* wrowp = w0 + (size_t)(ntile + lm) * 257;

    float acc[4][4] = {};

    for (int kk = 0; kk < 256; kk += 16) {
        float4 av = *reinterpret_cast<const float4*>(emb + (size_t)arow * EE + kk + lk);
        float wv0 = wrowp[kk + lk + 0];
        float wv1 = wrowp[kk + lk + 1];
        float wv2 = wrowp[kk + lk + 2];
        float wv3 = wrowp[kk + lk + 3];
        __syncthreads();
        As[lk + 0][lm] = av.x; As[lk + 1][lm] = av.y; As[lk + 2][lm] = av.z; As[lk + 3][lm] = av.w;
        Ws[lk + 0][lm] = wv0;  Ws[lk + 1][lm] = wv1;  Ws[lk + 2][lm] = wv2;  Ws[lk + 3][lm] = wv3;
        __syncthreads();
        #pragma unroll
        for (int k = 0; k < 16; ++k) {
            float a[4], w[4];
            #pragma unroll
            for (int i = 0; i < 4; ++i) { a[i] = As[k][(ty << 2) + i]; w[i] = Ws[k][(tx << 2) + i]; }
            #pragma unroll
            for (int i = 0; i < 4; ++i)
                #pragma unroll
                for (int j = 0; j < 4; ++j) acc[i][j] += a[i] * w[j];
        }
    }

    #pragma unroll
    for (int i = 0; i < 4; ++i) {
        const int m = mtile + (ty << 2) + i;
        const float tm = ts[(ty << 2) + i];
        #pragma unroll
        for (int j = 0; j < 4; ++j) {
            const int g = ntile + (tx << 2) + j;
            g_xp[(size_t)m * G3 + g] = acc[i][j] + tm * w0[(size_t)g * 257 + 256] + b0[g];
        }
    }
}

// ---------------------------------------------------------------------------
// proj1: g_xp[n,g] = sum_k g_h[n,k]*w1[g,k] + b1[g]      (K = 512)
// ---------------------------------------------------------------------------
__global__ void __launch_bounds__(256)
k_proj1(const float* __restrict__ w1, const float* __restrict__ b1)
{
    __shared__ float As[16][64];
    __shared__ float Ws[16][64];

    const int tid   = threadIdx.x;
    const int mtile = blockIdx.y * 64;
    const int ntile = blockIdx.x * 64;
    const int tx = tid & 15, ty = tid >> 4;
    const int lm = tid >> 2;
    const int lk = (tid & 3) << 2;

    const float* arow = g_h + (size_t)(mtile + lm) * HH;
    const float* wrow = w1  + (size_t)(ntile + lm) * HH;

    float acc[4][4] = {};

    for (int kk = 0; kk < HH; kk += 16) {
        float4 av = *reinterpret_cast<const float4*>(arow + kk + lk);
        float4 wv = *reinterpret_cast<const float4*>(wrow + kk + lk);
        __syncthreads();
        As[lk + 0][lm] = av.x; As[lk + 1][lm] = av.y; As[lk + 2][lm] = av.z; As[lk + 3][lm] = av.w;
        Ws[lk + 0][lm] = wv.x; Ws[lk + 1][lm] = wv.y; Ws[lk + 2][lm] = wv.z; Ws[lk + 3][lm] = wv.w;
        __syncthreads();
        #pragma unroll
        for (int k = 0; k < 16; ++k) {
            float a[4], w[4];
            #pragma unroll
            for (int i = 0; i < 4; ++i) { a[i] = As[k][(ty << 2) + i]; w[i] = Ws[k][(tx << 2) + i]; }
            #pragma unroll
            for (int i = 0; i < 4; ++i)
                #pragma unroll
                for (int j = 0; j < 4; ++j) acc[i][j] += a[i] * w[j];
        }
    }

    #pragma unroll
    for (int i = 0; i < 4; ++i) {
        const int m = mtile + (ty << 2) + i;
        #pragma unroll
        for (int j = 0; j < 4; ++j) {
            const int g = ntile + (tx << 2) + j;
            g_xp[(size_t)m * G3 + g] = acc[i][j] + b1[g];
        }
    }
}

// ---------------------------------------------------------------------------
// stepA: split-K partial GEMM  g_ghp[kc][b,g] = sum_{k in chunk} state[b,k]*whh[g,k]
// Grid (24, 4): 24 N-tiles of 64, 4 K-chunks of 128. BM = 64 = all batches.
// ---------------------------------------------------------------------------
__global__ void __launch_bounds__(256)
k_stepA(const float* __restrict__ whh)
{
    __shared__ float As[16][64];
    __shared__ float Ws[16][64];

    const int tid   = threadIdx.x;
    const int ntile = blockIdx.x * 64;
    const int kc    = blockIdx.y;
    const int kbase = kc * 128;
    const int tx = tid & 15, ty = tid >> 4;
    const int lm = tid >> 2;
    const int lk = (tid & 3) << 2;

    const float* arow = g_state + lm * HH + kbase;
    const float* wrow = whh + (size_t)(ntile + lm) * HH + kbase;

    float acc[4][4] = {};

    for (int kk = 0; kk < 128; kk += 16) {
        float4 av = *reinterpret_cast<const float4*>(arow + kk + lk);
        float4 wv = *reinterpret_cast<const float4*>(wrow + kk + lk);
        __syncthreads();
        As[lk + 0][lm] = av.x; As[lk + 1][lm] = av.y; As[lk + 2][lm] = av.z; As[lk + 3][lm] = av.w;
        Ws[lk + 0][lm] = wv.x; Ws[lk + 1][lm] = wv.y; Ws[lk + 2][lm] = wv.z; Ws[lk + 3][lm] = wv.w;
        __syncthreads();
        #pragma unroll
        for (int k = 0; k < 16; ++k) {
            float a[4], w[4];
            #pragma unroll
            for (int i = 0; i < 4; ++i) { a[i] = As[k][(ty << 2) + i]; w[i] = Ws[k][(tx << 2) + i]; }
            #pragma unroll
            for (int i = 0; i < 4; ++i)
                #pragma unroll
                for (int j = 0; j < 4; ++j) acc[i][j] += a[i] * w[j];
        }
    }

    #pragma unroll
    for (int i = 0; i < 4; ++i) {
        const int m = (ty << 2) + i;       // batch index
        #pragma unroll
        for (int j = 0; j < 4; ++j) {
            const int g = ntile + (tx << 2) + j;
            g_ghp[kc][m * G3 + g] = acc[i][j];
        }
    }
}

// ---------------------------------------------------------------------------
// stepB: combine split-K partials, apply GRU gates, update state, store h_t.
// 32768 threads: idx -> (b, j).
// ---------------------------------------------------------------------------
__global__ void __launch_bounds__(256)
k_stepB(const float* __restrict__ bhh, int t)
{
    const int idx = blockIdx.x * blockDim.x + threadIdx.x;
    const int b = idx >> 9;
    const int j = idx & 511;
    const int n = b * TT + t;

    const int base = b * G3 + j;
    float sr = g_ghp[0][base]        + g_ghp[1][base]        + g_ghp[2][base]        + g_ghp[3][base]        + bhh[j];
    float sz = g_ghp[0][base + 512]  + g_ghp[1][base + 512]  + g_ghp[2][base + 512]  + g_ghp[3][base + 512]  + bhh[512 + j];
    float sn = g_ghp[0][base + 1024] + g_ghp[1][base + 1024] + g_ghp[2][base + 1024] + g_ghp[3][base + 1024] + bhh[1024 + j];

    const float* xp = g_xp + (size_t)n * G3;
    float r  = 1.0f / (1.0f + expf(-(xp[j] + sr)));
    float z  = 1.0f / (1.0f + expf(-(xp[512 + j] + sz)));
    float nn = tanhf(xp[1024 + j] + r * sn);

    float hold = g_state[idx];
    float hnew = (1.0f - z) * nn + z * hold;
    g_state[idx] = hnew;
    g_h[(size_t)n * HH + j] = hnew;
}

// ---------------------------------------------------------------------------
// FC: out[n,g] = relu(g_h[n,:]) . fc_w[g,:] + fc_b[g]
// BM=128, BN=128, BK=8, 256 threads, 8x8 per thread. g==10000 -> time region.
// ---------------------------------------------------------------------------
__global__ void __launch_bounds__(256)
k_fc(const float* __restrict__ fw, const float* __restrict__ fb,
     float* __restrict__ out)
{
    __shared__ float As[8][128];
    __shared__ float Ws[8][128];

    const int tid   = threadIdx.x;
    const int mtile = blockIdx.y * 128;
    const int ntile = blockIdx.x * 128;
    const int tx = tid & 15, ty = tid >> 4;
    const int lm = tid >> 1;             // 0..127
    const int lk = (tid & 1) << 2;       // 0 or 4

    const float* arow = g_h + (size_t)(mtile + lm) * HH;
    const int gl = ntile + lm;
    const bool wok = (gl < VOUT);
    const float* wrow = fw + (size_t)(wok ? gl : 0) * HH;

    float acc[8][8] = {};

    for (int kk = 0; kk < HH; kk += 8) {
        float4 av = *reinterpret_cast<const float4*>(arow + kk + lk);
        float4 wv = *reinterpret_cast<const float4*>(wrow + kk + lk);
        if (!wok) { wv.x = 0.f; wv.y = 0.f; wv.z = 0.f; wv.w = 0.f; }
        __syncthreads();
        As[lk + 0][lm] = fmaxf(av.x, 0.f);
        As[lk + 1][lm] = fmaxf(av.y, 0.f);
        As[lk + 2][lm] = fmaxf(av.z, 0.f);
        As[lk + 3][lm] = fmaxf(av.w, 0.f);
        Ws[lk + 0][lm] = wv.x; Ws[lk + 1][lm] = wv.y; Ws[lk + 2][lm] = wv.z; Ws[lk + 3][lm] = wv.w;
        __syncthreads();
        #pragma unroll
        for (int k = 0; k < 8; ++k) {
            float a[8], w[8];
            #pragma unroll
            for (int i = 0; i < 8; ++i) a[i] = As[k][(ty << 3) + i];
            #pragma unroll
            for (int j = 0; j < 8; ++j) w[j] = Ws[k][(tx << 3) + j];
            #pragma unroll
            for (int i = 0; i < 8; ++i)
                #pragma unroll
                for (int j = 0; j < 8; ++j) acc[i][j] += a[i] * w[j];
        }
    }

    #pragma unroll
    for (int i = 0; i < 8; ++i) {
        const int m = mtile + (ty << 3) + i;
        #pragma unroll
        for (int j = 0; j < 8; ++j) {
            const int g = ntile + (tx << 3) + j;
            if (g < VOUT) {
                float c = acc[i][j] + fb[g];
                if (g < VN) out[(size_t)m * VN + g] = c;
                else        out[K_LOC_ELEMS + m] = c;    // raw time logit
            }
        }
    }
}

// ---------------------------------------------------------------------------
// Softmax: per-row log_softmax with the whole 40KB row cached in smem
// (1 read + 1 write of the 328MB output). Also sigmoid on the time logit.
// ---------------------------------------------------------------------------
__global__ void __launch_bounds__(256)
k_softmax(float* __restrict__ out)
{
    extern __shared__ float row[];       // VN floats
    __shared__ float red[256];

    const int n = blockIdx.x;
    const int tid = threadIdx.x;
    float* base = out + (size_t)n * VN;

    float mx = -1e30f;
    for (int i = tid; i < VN; i += 256) { float v = base[i]; row[i] = v; mx = fmaxf(mx, v); }
    red[tid] = mx; __syncthreads();
    for (int s = 128; s > 0; s >>= 1) { if (tid < s) red[tid] = fmaxf(red[tid], red[tid + s]); __syncthreads(); }
    mx = red[0];
    __syncthreads();

    float sum = 0.f;
    for (int i = tid; i < VN; i += 256) sum += expf(row[i] - mx);
    red[tid] = sum; __syncthreads();
    for (int s = 128; s > 0; s >>= 1) { if (tid < s) red[tid] += red[tid + s]; __syncthreads(); }
    float lse = mx + logf(red[0]);

    for (int i = tid; i < VN; i += 256) base[i] = row[i] - lse;

    if (tid == 0) {
        float tl = out[K_LOC_ELEMS + n];
        out[K_LOC_ELEMS + n] = 1.0f / (1.0f + expf(-tl));
    }
}

// ---------------------------------------------------------------------------
// Launch
// ---------------------------------------------------------------------------
extern "C" void kernel_launch(void* const* d_in, const int* in_sizes, int n_in,
                              void* d_out, int out_size)
{
    const int*   loc   = (const int*)  d_in[0];
    const float* times = (const float*)d_in[1];
    const float* emb   = (const float*)d_in[2];
    const float* w_ih0 = (const float*)d_in[3];
    const float* w_hh0 = (const float*)d_in[4];
    const float* b_ih0 = (const float*)d_in[5];
    const float* b_hh0 = (const float*)d_in[6];
    const float* w_ih1 = (const float*)d_in[7];
    const float* w_hh1 = (const float*)d_in[8];
    const float* b_ih1 = (const float*)d_in[9];
    const float* b_hh1 = (const float*)d_in[10];
    const float* fc_w  = (const float*)d_in[11];
    const float* fc_b  = (const float*)d_in[12];
    float* out = (float*)d_out;

    // Layer 0: input projection (fused embedding gather)
    k_proj0<<<dim3(G3 / 64, NR / 64), 256>>>(loc, times, emb, w_ih0, b_ih0);

    // Layer 0 recurrence
    k_zero_state<<<(BB * HH + 255) / 256, 256>>>();
    for (int t = 0; t < TT; ++t) {
        k_stepA<<<dim3(G3 / 64, 4), 256>>>(w_hh0);
        k_stepB<<<(BB * HH) / 256, 256>>>(b_hh0, t);
    }

    // Layer 1: input projection from h1
    k_proj1<<<dim3(G3 / 64, NR / 64), 256>>>(w_ih1, b_ih1);

    // Layer 1 recurrence (overwrites g_h with h2)
    k_zero_state<<<(BB * HH + 255) / 256, 256>>>();
    for (int t = 0; t < TT; ++t) {
        k_stepA<<<dim3(G3 / 64, 4), 256>>>(w_hh1);
        k_stepB<<<(BB * HH) / 256, 256>>>(b_hh1, t);
    }

    // FC -> logits straight into d_out
    k_fc<<<dim3((VOUT + 127) / 128, NR / 128), 256>>>(fc_w, fc_b, out);

    // log_softmax + time sigmoid
    k_softmax<<<NR, 256, VN * sizeof(float)>>>(out);
}